// round 13
// baseline (speedup 1.0000x reference)
#include <cuda_runtime.h>
#include <cuda_bf16.h>

#define T_DIM 1024
#define B_DIM 64
#define H_DIM 1024
#define OSPLIT 32                 // o-range per k1 block
#define K1_HT 128                 // h-tile per k1 block
#define TPW 8                     // t-rows per warp in k2 (R8 winner)
#define K1_NCTA 512               // compute CTAs in K_A
#define NRED 256                  // reducer CTAs in K_A
#define CHUNKS_PER_B (T_DIM / (8 * TPW))   // 16

// Scratch (allocation-free rule: __device__ globals; zero-initialized)
__device__ float g_partial[OSPLIT * B_DIM * H_DIM];  // 8 MB: [s][b][h]
__device__ float g_v[B_DIM * H_DIM];                 // 256 KB
__device__ float g_energies[B_DIM * T_DIM];          // 256 KB: [b][t]
__device__ unsigned g_k1_done;                       // K_A arrivals
__device__ unsigned g_red_done;                      // K_A reducer arrivals
__device__ unsigned g_cnt[B_DIM];                    // K_B per-b arrivals
__device__ unsigned g_sm_done;                       // K_B softmax arrivals

// ---------------------------------------------------------------------------
// K_A: k1 (proj partials) + k1b (reduction) in ONE launch.
// z<2: compute CTAs (R11 body, byte-identical math).
// z==2: 256 reducer CTAs spin until all 512 compute CTAs arrive, then reduce.
// All 768 CTAs co-reside (128 thr, ~80 regs -> ~6/SM): no deadlock risk.
// Last reducer resets both counters for the next graph replay.
// ---------------------------------------------------------------------------
__global__ void __launch_bounds__(K1_HT) kA_proj(
    const float* __restrict__ hid, const float* __restrict__ W)
{
    if (blockIdx.z < 2) {
        // ---- k1 compute (R11 body) ----
        const int h  = blockIdx.x * K1_HT + threadIdx.x;
        const int o0 = blockIdx.y * OSPLIT;
        const int b0 = blockIdx.z * 32;

        __shared__ float sh[32 * OSPLIT];   // 4 KB
        for (int i = threadIdx.x; i < 32 * OSPLIT; i += K1_HT) {
            int bb = i >> 5;
            int oo = i & 31;
            sh[i] = hid[(b0 + bb) * H_DIM + o0 + oo];
        }
        __syncthreads();

        float w[OSPLIT];
#pragma unroll
        for (int oo = 0; oo < OSPLIT; oo++)
            w[oo] = W[(o0 + oo) * H_DIM + h];

        float* part = g_partial + blockIdx.y * (B_DIM * H_DIM) + h;

#pragma unroll
        for (int bb = 0; bb < 32; bb++) {
            const float4* s4 = reinterpret_cast<const float4*>(sh + bb * OSPLIT);
            float4 x0 = s4[0], x1 = s4[1], x2 = s4[2], x3 = s4[3];
            float4 x4 = s4[4], x5 = s4[5], x6 = s4[6], x7 = s4[7];
            float a0 = 0.f, a1 = 0.f, a2 = 0.f, a3 = 0.f;
            a0 += x0.x * w[0]  + x0.y * w[1]  + x0.z * w[2]  + x0.w * w[3];
            a1 += x1.x * w[4]  + x1.y * w[5]  + x1.z * w[6]  + x1.w * w[7];
            a2 += x2.x * w[8]  + x2.y * w[9]  + x2.z * w[10] + x2.w * w[11];
            a3 += x3.x * w[12] + x3.y * w[13] + x3.z * w[14] + x3.w * w[15];
            a0 += x4.x * w[16] + x4.y * w[17] + x4.z * w[18] + x4.w * w[19];
            a1 += x5.x * w[20] + x5.y * w[21] + x5.z * w[22] + x5.w * w[23];
            a2 += x6.x * w[24] + x6.y * w[25] + x6.z * w[26] + x6.w * w[27];
            a3 += x7.x * w[28] + x7.y * w[29] + x7.z * w[30] + x7.w * w[31];
            part[(b0 + bb) * H_DIM] = (a0 + a1) + (a2 + a3);
        }

        // release: publish partials, then arrive
        __threadfence();
        __syncthreads();
        if (threadIdx.x == 0)
            atomicAdd(&g_k1_done, 1u);
        return;
    }

    // ---- reducer CTA: r in 0..255 handles 256 consecutive v elements ----
    const int r = blockIdx.x + 8 * blockIdx.y;      // 0..255

    if (threadIdx.x == 0) {
        while (atomicAdd(&g_k1_done, 0u) < K1_NCTA)
            __nanosleep(64);
    }
    __syncthreads();
    __threadfence();     // acquire: see all compute CTAs' partials

    const int base = r * 256;
#pragma unroll
    for (int e = 0; e < 2; e++) {
        int i = base + threadIdx.x + e * K1_HT;
        float s0 = 0.f, s1 = 0.f, s2 = 0.f, s3 = 0.f;
#pragma unroll
        for (int p = 0; p < OSPLIT; p += 4) {
            s0 += g_partial[(p + 0) * (B_DIM * H_DIM) + i];
            s1 += g_partial[(p + 1) * (B_DIM * H_DIM) + i];
            s2 += g_partial[(p + 2) * (B_DIM * H_DIM) + i];
            s3 += g_partial[(p + 3) * (B_DIM * H_DIM) + i];
        }
        g_v[i] = (s0 + s1) + (s2 + s3);
    }

    // last reducer resets K_A counters for next graph replay
    __threadfence();
    __syncthreads();
    if (threadIdx.x == 0) {
        unsigned old = atomicAdd(&g_red_done, 1u);
        if (old == NRED - 1) {
            g_k1_done = 0u;
            g_red_done = 0u;
        }
    }
}

// ---------------------------------------------------------------------------
// K_B: k2 (energies) + k3 (softmax) in ONE launch.
// y<16: R8's k2 CTA (byte-identical inner loop) + one arrival at the end.
// y==16: softmax CTA for row b — spins until its 16 producers arrive,
//        then 256 threads x 1 float4 softmax (L2-hot), writes d_out.
// Softmax CTAs are the last 64 bids -> scheduled last; spins are brief.
// Last softmax CTA resets g_cnt[] and g_sm_done for the next replay.
// Bias dropped (softmax shift invariance).
// ---------------------------------------------------------------------------
__global__ void __launch_bounds__(256) kB_energies_softmax(
    const float* __restrict__ enc, float* __restrict__ out)
{
    const int warp = threadIdx.x >> 5;
    const int lane = threadIdx.x & 31;
    const int b    = blockIdx.x;                       // 0..63

    if (blockIdx.y < CHUNKS_PER_B) {
        // ---- k2 compute (R8 body) ----
        const int t0 = blockIdx.y * (8 * TPW) + warp * TPW;

        const float4* v4 = reinterpret_cast<const float4*>(g_v + b * H_DIM);
        float4 v[8];
#pragma unroll
        for (int k = 0; k < 8; k++)
            v[k] = v4[lane + 32 * k];

        const float4* e4 = reinterpret_cast<const float4*>(
            enc + (size_t)(t0 * B_DIM + b) * H_DIM) + lane;
        const size_t row_stride4 = (size_t)B_DIM * H_DIM / 4;

        float* eout = g_energies + b * T_DIM + t0;

#pragma unroll 4
        for (int i = 0; i < TPW; i++) {
            float acc = 0.f;
#pragma unroll
            for (int k = 0; k < 8; k++) {
                float4 x = __ldcs(e4 + 32 * k);
                acc += x.x * v[k].x + x.y * v[k].y + x.z * v[k].z + x.w * v[k].w;
            }
#pragma unroll
            for (int off = 16; off; off >>= 1)
                acc += __shfl_xor_sync(0xffffffffu, acc, off);
            if (lane == 0)
                eout[i] = acc;
            e4 += row_stride4;
        }

        // release: publish energies, then arrive on this b's counter
        __threadfence();
        __syncthreads();
        if (threadIdx.x == 0)
            atomicAdd(&g_cnt[b], 1u);
        return;
    }

    // ---- softmax CTA for row b ----
    if (threadIdx.x == 0) {
        while (atomicAdd(&g_cnt[b], 0u) < CHUNKS_PER_B)
            __nanosleep(64);
    }
    __syncthreads();
    __threadfence();     // acquire: see all 16 producers' energy stores

    const int tid = threadIdx.x;
    __shared__ float sred[8];

    float4 x = reinterpret_cast<const float4*>(g_energies + b * T_DIM)[tid];

    float m = fmaxf(fmaxf(x.x, x.y), fmaxf(x.z, x.w));
#pragma unroll
    for (int off = 16; off; off >>= 1)
        m = fmaxf(m, __shfl_xor_sync(0xffffffffu, m, off));
    if (lane == 0) sred[warp] = m;
    __syncthreads();
    m = sred[0];
#pragma unroll
    for (int w2 = 1; w2 < 8; w2++)
        m = fmaxf(m, sred[w2]);
    __syncthreads();

    x.x = __expf(x.x - m);
    x.y = __expf(x.y - m);
    x.z = __expf(x.z - m);
    x.w = __expf(x.w - m);
    float lsum = x.x + x.y + x.z + x.w;
#pragma unroll
    for (int off = 16; off; off >>= 1)
        lsum += __shfl_xor_sync(0xffffffffu, lsum, off);
    if (lane == 0) sred[warp] = lsum;
    __syncthreads();
    float tot = 0.f;
#pragma unroll
    for (int w2 = 0; w2 < 8; w2++)
        tot += sred[w2];
    const float inv = 1.f / tot;

    x.x *= inv; x.y *= inv; x.z *= inv; x.w *= inv;
    reinterpret_cast<float4*>(out + b * T_DIM)[tid] = x;

    // last softmax CTA resets K_B counters for the next replay
    __threadfence();
    __syncthreads();
    if (threadIdx.x == 0) {
        unsigned old = atomicAdd(&g_sm_done, 1u);
        if (old == B_DIM - 1) {
            for (int i = 0; i < B_DIM; i++)
                g_cnt[i] = 0u;
            g_sm_done = 0u;
        }
    }
}

// ---------------------------------------------------------------------------
extern "C" void kernel_launch(void* const* d_in, const int* in_sizes, int n_in,
                              void* d_out, int out_size)
{
    const float* hid = (const float*)d_in[0];   // [1, B, H]
    const float* enc = (const float*)d_in[1];   // [T, B, H]
    const float* W   = (const float*)d_in[2];   // [H, H]
    // d_in[3] = bias: dropped — softmax shift-invariance makes it a no-op.
    float* out = (float*)d_out;                 // [B, 1, T]

    kA_proj<<<dim3(H_DIM / K1_HT, OSPLIT, 3), K1_HT>>>(hid, W);
    kB_energies_softmax<<<dim3(B_DIM, CHUNKS_PER_B + 1), 256>>>(enc, out);
}

// round 14
// speedup vs baseline: 1.0515x; 1.0515x over previous
#include <cuda_runtime.h>
#include <cuda_bf16.h>

#define T_DIM 1024
#define B_DIM 64
#define H_DIM 1024
#define OSPLIT 32                 // o-range per k1 block
#define K1_HT 128                 // h-tile per k1 block
#define TPW 8                     // t-rows per warp in k2 (R8 winner)
#define CHUNKS_PER_B (T_DIM / (8 * TPW))   // 16

// Scratch (allocation-free rule: __device__ globals; zero-initialized)
__device__ float g_partial[OSPLIT * B_DIM * H_DIM];  // 8 MB: [s][b][h]
__device__ float g_v[B_DIM * H_DIM];                 // 256 KB
__device__ float g_energies[B_DIM * T_DIM];          // 256 KB: [b][t]
__device__ unsigned g_cnt[B_DIM];                    // kB per-b arrivals
__device__ unsigned g_sm_done;                       // kB softmax arrivals

// ---------------------------------------------------------------------------
// k1: partial[s][b][h] = sum_{o in s-range} hid[b][o] * W[o][h]
// grid (8, 32, 2) = 512 CTAs x 128 threads; 4 indep FFMA chains per bb.
// (R11 version — no spinning reducers; R13 proved co-resident spinners lose.)
// ---------------------------------------------------------------------------
__global__ void __launch_bounds__(K1_HT) k1_proj_partial(
    const float* __restrict__ hid, const float* __restrict__ W)
{
    const int h  = blockIdx.x * K1_HT + threadIdx.x;
    const int o0 = blockIdx.y * OSPLIT;
    const int b0 = blockIdx.z * 32;

    __shared__ float sh[32 * OSPLIT];   // 4 KB
    for (int i = threadIdx.x; i < 32 * OSPLIT; i += K1_HT) {
        int bb = i >> 5;
        int oo = i & 31;
        sh[i] = hid[(b0 + bb) * H_DIM + o0 + oo];
    }
    __syncthreads();

    float w[OSPLIT];
#pragma unroll
    for (int oo = 0; oo < OSPLIT; oo++)
        w[oo] = W[(o0 + oo) * H_DIM + h];

    float* part = g_partial + blockIdx.y * (B_DIM * H_DIM) + h;

#pragma unroll
    for (int bb = 0; bb < 32; bb++) {
        const float4* s4 = reinterpret_cast<const float4*>(sh + bb * OSPLIT);
        float4 x0 = s4[0], x1 = s4[1], x2 = s4[2], x3 = s4[3];
        float4 x4 = s4[4], x5 = s4[5], x6 = s4[6], x7 = s4[7];
        float a0 = 0.f, a1 = 0.f, a2 = 0.f, a3 = 0.f;
        a0 += x0.x * w[0]  + x0.y * w[1]  + x0.z * w[2]  + x0.w * w[3];
        a1 += x1.x * w[4]  + x1.y * w[5]  + x1.z * w[6]  + x1.w * w[7];
        a2 += x2.x * w[8]  + x2.y * w[9]  + x2.z * w[10] + x2.w * w[11];
        a3 += x3.x * w[12] + x3.y * w[13] + x3.z * w[14] + x3.w * w[15];
        a0 += x4.x * w[16] + x4.y * w[17] + x4.z * w[18] + x4.w * w[19];
        a1 += x5.x * w[20] + x5.y * w[21] + x5.z * w[22] + x5.w * w[23];
        a2 += x6.x * w[24] + x6.y * w[25] + x6.z * w[26] + x6.w * w[27];
        a3 += x7.x * w[28] + x7.y * w[29] + x7.z * w[30] + x7.w * w[31];
        part[(b0 + bb) * H_DIM] = (a0 + a1) + (a2 + a3);
    }
}

// ---------------------------------------------------------------------------
// k1b: v[i] = sum_s partial[s][i]  (R11 version; deterministic)
// ---------------------------------------------------------------------------
__global__ void __launch_bounds__(256) k1b_reduce()
{
    int i = blockIdx.x * 256 + threadIdx.x;  // 65536 total
    float s0 = 0.f, s1 = 0.f, s2 = 0.f, s3 = 0.f;
#pragma unroll
    for (int p = 0; p < OSPLIT; p += 4) {
        s0 += g_partial[(p + 0) * (B_DIM * H_DIM) + i];
        s1 += g_partial[(p + 1) * (B_DIM * H_DIM) + i];
        s2 += g_partial[(p + 2) * (B_DIM * H_DIM) + i];
        s3 += g_partial[(p + 3) * (B_DIM * H_DIM) + i];
    }
    g_v[i] = (s0 + s1) + (s2 + s3);
}

// ---------------------------------------------------------------------------
// kB: k2 (energies) + k3 (softmax) in ONE launch (R13's winning half, 47.1us
// at DRAM=73%). y<16: R8 k2 CTA + arrival. y==16 (last 64 bids): per-b
// softmax CTA spins for its 16 producers, then 256 thr x float4 softmax.
// Last softmax CTA resets counters for the next graph replay.
// Bias dropped (softmax shift invariance).
// ---------------------------------------------------------------------------
__global__ void __launch_bounds__(256) kB_energies_softmax(
    const float* __restrict__ enc, float* __restrict__ out)
{
    const int warp = threadIdx.x >> 5;
    const int lane = threadIdx.x & 31;
    const int b    = blockIdx.x;                       // 0..63

    if (blockIdx.y < CHUNKS_PER_B) {
        // ---- k2 compute (R8 body) ----
        const int t0 = blockIdx.y * (8 * TPW) + warp * TPW;

        const float4* v4 = reinterpret_cast<const float4*>(g_v + b * H_DIM);
        float4 v[8];
#pragma unroll
        for (int k = 0; k < 8; k++)
            v[k] = v4[lane + 32 * k];

        const float4* e4 = reinterpret_cast<const float4*>(
            enc + (size_t)(t0 * B_DIM + b) * H_DIM) + lane;
        const size_t row_stride4 = (size_t)B_DIM * H_DIM / 4;

        float* eout = g_energies + b * T_DIM + t0;

#pragma unroll 4
        for (int i = 0; i < TPW; i++) {
            float acc = 0.f;
#pragma unroll
            for (int k = 0; k < 8; k++) {
                float4 x = __ldcs(e4 + 32 * k);
                acc += x.x * v[k].x + x.y * v[k].y + x.z * v[k].z + x.w * v[k].w;
            }
#pragma unroll
            for (int off = 16; off; off >>= 1)
                acc += __shfl_xor_sync(0xffffffffu, acc, off);
            if (lane == 0)
                eout[i] = acc;
            e4 += row_stride4;
        }

        // release: publish energies, then arrive on this b's counter
        __threadfence();
        __syncthreads();
        if (threadIdx.x == 0)
            atomicAdd(&g_cnt[b], 1u);
        return;
    }

    // ---- softmax CTA for row b ----
    if (threadIdx.x == 0) {
        while (atomicAdd(&g_cnt[b], 0u) < CHUNKS_PER_B)
            __nanosleep(64);
    }
    __syncthreads();
    __threadfence();     // acquire: see all 16 producers' energy stores

    const int tid = threadIdx.x;
    __shared__ float sred[8];

    float4 x = reinterpret_cast<const float4*>(g_energies + b * T_DIM)[tid];

    float m = fmaxf(fmaxf(x.x, x.y), fmaxf(x.z, x.w));
#pragma unroll
    for (int off = 16; off; off >>= 1)
        m = fmaxf(m, __shfl_xor_sync(0xffffffffu, m, off));
    if (lane == 0) sred[warp] = m;
    __syncthreads();
    m = sred[0];
#pragma unroll
    for (int w2 = 1; w2 < 8; w2++)
        m = fmaxf(m, sred[w2]);
    __syncthreads();

    x.x = __expf(x.x - m);
    x.y = __expf(x.y - m);
    x.z = __expf(x.z - m);
    x.w = __expf(x.w - m);
    float lsum = x.x + x.y + x.z + x.w;
#pragma unroll
    for (int off = 16; off; off >>= 1)
        lsum += __shfl_xor_sync(0xffffffffu, lsum, off);
    if (lane == 0) sred[warp] = lsum;
    __syncthreads();
    float tot = 0.f;
#pragma unroll
    for (int w2 = 0; w2 < 8; w2++)
        tot += sred[w2];
    const float inv = 1.f / tot;

    x.x *= inv; x.y *= inv; x.z *= inv; x.w *= inv;
    reinterpret_cast<float4*>(out + b * T_DIM)[tid] = x;

    // last softmax CTA resets counters for the next replay
    __threadfence();
    __syncthreads();
    if (threadIdx.x == 0) {
        unsigned old = atomicAdd(&g_sm_done, 1u);
        if (old == B_DIM - 1) {
            for (int i = 0; i < B_DIM; i++)
                g_cnt[i] = 0u;
            g_sm_done = 0u;
        }
    }
}

// ---------------------------------------------------------------------------
extern "C" void kernel_launch(void* const* d_in, const int* in_sizes, int n_in,
                              void* d_out, int out_size)
{
    const float* hid = (const float*)d_in[0];   // [1, B, H]
    const float* enc = (const float*)d_in[1];   // [T, B, H]
    const float* W   = (const float*)d_in[2];   // [H, H]
    // d_in[3] = bias: dropped — softmax shift-invariance makes it a no-op.
    float* out = (float*)d_out;                 // [B, 1, T]

    k1_proj_partial<<<dim3(H_DIM / K1_HT, OSPLIT, 2), K1_HT>>>(hid, W);
    k1b_reduce<<<(B_DIM * H_DIM) / 256, 256>>>();
    kB_energies_softmax<<<dim3(B_DIM, CHUNKS_PER_B + 1), 256>>>(enc, out);
}

// round 15
// speedup vs baseline: 1.0732x; 1.0207x over previous
#include <cuda_runtime.h>
#include <cuda_bf16.h>

#define T_DIM 1024
#define B_DIM 64
#define H_DIM 1024
#define NSPL 64                   // o-splits in k1 (16 o each)
#define OO 16                     // o per split
#define BB 16                     // b per k1 CTA
#define TPW 8                     // t-rows per warp in kB (R8 winner)
#define CHUNKS_PER_B (T_DIM / (8 * TPW))   // 16

// Scratch (allocation-free rule: __device__ globals; zero-initialized)
__device__ float g_partial[NSPL * B_DIM * H_DIM];    // 16 MB: [s][b][h]
__device__ float g_v[B_DIM * H_DIM];                 // 256 KB
__device__ float g_energies[B_DIM * T_DIM];          // 256 KB: [b][t]
__device__ unsigned g_cnt[B_DIM];                    // kB per-b arrivals
__device__ unsigned g_sm_done;                       // kB softmax arrivals

// ---------------------------------------------------------------------------
// k1: partial[s][b][h] = sum_{o in s-range} hid[b][o] * W[o][h]
// NEW SHAPE: each thread owns a float4 of h. Per bb: 4 broadcast LDS.128
// feed 64 FFMAs (ratio 16:1 vs old 4:1) — smem crossbar pressure /4,
// which the R14 profile showed was k1's binding resource (L1=28.6%).
// grid (2, 64, 4) = 512 CTAs x 128 thr; w4[16] = 64 regs.
// ---------------------------------------------------------------------------
__global__ void __launch_bounds__(128) k1_proj_partial(
    const float* __restrict__ hid, const float* __restrict__ W)
{
    const int h0 = (blockIdx.x * 128 + threadIdx.x) * 4;   // float4 of h
    const int o0 = blockIdx.y * OO;
    const int b0 = blockIdx.z * BB;

    __shared__ float sh[BB * OO];   // 1 KB
    for (int i = threadIdx.x; i < BB * OO; i += 128) {
        int bb = i / OO;
        int oo = i % OO;
        sh[i] = hid[(b0 + bb) * H_DIM + o0 + oo];
    }
    __syncthreads();

    // W rows for this split, float4-wide in h (coalesced LDG.128)
    float4 w4[OO];
#pragma unroll
    for (int oo = 0; oo < OO; oo++)
        w4[oo] = *reinterpret_cast<const float4*>(W + (size_t)(o0 + oo) * H_DIM + h0);

    float4* part = reinterpret_cast<float4*>(
        g_partial + (size_t)blockIdx.y * (B_DIM * H_DIM) + h0);

#pragma unroll
    for (int bb = 0; bb < BB; bb++) {
        const float4* s4 = reinterpret_cast<const float4*>(sh + bb * OO);
        float4 hv0 = s4[0], hv1 = s4[1], hv2 = s4[2], hv3 = s4[3];
        float4 a = make_float4(0.f, 0.f, 0.f, 0.f);
#define FMA4(hs, oo)                                                   \
        a.x += (hs) * w4[oo].x; a.y += (hs) * w4[oo].y;                \
        a.z += (hs) * w4[oo].z; a.w += (hs) * w4[oo].w;
        FMA4(hv0.x, 0)  FMA4(hv0.y, 1)  FMA4(hv0.z, 2)  FMA4(hv0.w, 3)
        FMA4(hv1.x, 4)  FMA4(hv1.y, 5)  FMA4(hv1.z, 6)  FMA4(hv1.w, 7)
        FMA4(hv2.x, 8)  FMA4(hv2.y, 9)  FMA4(hv2.z, 10) FMA4(hv2.w, 11)
        FMA4(hv3.x, 12) FMA4(hv3.y, 13) FMA4(hv3.z, 14) FMA4(hv3.w, 15)
#undef FMA4
        part[(size_t)(b0 + bb) * (H_DIM / 4)] = a;
    }
}

// ---------------------------------------------------------------------------
// k1b: v[i] = sum_s partial[s][i]  over 64 splits (deterministic)
// ---------------------------------------------------------------------------
__global__ void __launch_bounds__(256) k1b_reduce()
{
    int i = blockIdx.x * 256 + threadIdx.x;  // 65536 total
    float s0 = 0.f, s1 = 0.f, s2 = 0.f, s3 = 0.f;
    float s4 = 0.f, s5 = 0.f, s6 = 0.f, s7 = 0.f;
#pragma unroll
    for (int p = 0; p < NSPL; p += 8) {
        s0 += g_partial[(size_t)(p + 0) * (B_DIM * H_DIM) + i];
        s1 += g_partial[(size_t)(p + 1) * (B_DIM * H_DIM) + i];
        s2 += g_partial[(size_t)(p + 2) * (B_DIM * H_DIM) + i];
        s3 += g_partial[(size_t)(p + 3) * (B_DIM * H_DIM) + i];
        s4 += g_partial[(size_t)(p + 4) * (B_DIM * H_DIM) + i];
        s5 += g_partial[(size_t)(p + 5) * (B_DIM * H_DIM) + i];
        s6 += g_partial[(size_t)(p + 6) * (B_DIM * H_DIM) + i];
        s7 += g_partial[(size_t)(p + 7) * (B_DIM * H_DIM) + i];
    }
    g_v[i] = ((s0 + s1) + (s2 + s3)) + ((s4 + s5) + (s6 + s7));
}

// ---------------------------------------------------------------------------
// kB: k2 (energies) + k3 (softmax) in ONE launch (R13/R14 proven: 47.1us,
// DRAM=73%). y<16: R8 k2 CTA + arrival. y==16 (last 64 bids): per-b softmax
// CTA spins for its 16 producers, then 256 thr x float4 softmax.
// Last softmax CTA resets counters for the next graph replay.
// Bias dropped (softmax shift invariance).
// ---------------------------------------------------------------------------
__global__ void __launch_bounds__(256) kB_energies_softmax(
    const float* __restrict__ enc, float* __restrict__ out)
{
    const int warp = threadIdx.x >> 5;
    const int lane = threadIdx.x & 31;
    const int b    = blockIdx.x;                       // 0..63

    if (blockIdx.y < CHUNKS_PER_B) {
        // ---- k2 compute (R8 body) ----
        const int t0 = blockIdx.y * (8 * TPW) + warp * TPW;

        const float4* v4 = reinterpret_cast<const float4*>(g_v + b * H_DIM);
        float4 v[8];
#pragma unroll
        for (int k = 0; k < 8; k++)
            v[k] = v4[lane + 32 * k];

        const float4* e4 = reinterpret_cast<const float4*>(
            enc + (size_t)(t0 * B_DIM + b) * H_DIM) + lane;
        const size_t row_stride4 = (size_t)B_DIM * H_DIM / 4;

        float* eout = g_energies + b * T_DIM + t0;

#pragma unroll 4
        for (int i = 0; i < TPW; i++) {
            float acc = 0.f;
#pragma unroll
            for (int k = 0; k < 8; k++) {
                float4 x = __ldcs(e4 + 32 * k);
                acc += x.x * v[k].x + x.y * v[k].y + x.z * v[k].z + x.w * v[k].w;
            }
#pragma unroll
            for (int off = 16; off; off >>= 1)
                acc += __shfl_xor_sync(0xffffffffu, acc, off);
            if (lane == 0)
                eout[i] = acc;
            e4 += row_stride4;
        }

        // release: publish energies, then arrive on this b's counter
        __threadfence();
        __syncthreads();
        if (threadIdx.x == 0)
            atomicAdd(&g_cnt[b], 1u);
        return;
    }

    // ---- softmax CTA for row b ----
    if (threadIdx.x == 0) {
        while (atomicAdd(&g_cnt[b], 0u) < CHUNKS_PER_B)
            __nanosleep(64);
    }
    __syncthreads();
    __threadfence();     // acquire: see all 16 producers' energy stores

    const int tid = threadIdx.x;
    __shared__ float sred[8];

    float4 x = reinterpret_cast<const float4*>(g_energies + b * T_DIM)[tid];

    float m = fmaxf(fmaxf(x.x, x.y), fmaxf(x.z, x.w));
#pragma unroll
    for (int off = 16; off; off >>= 1)
        m = fmaxf(m, __shfl_xor_sync(0xffffffffu, m, off));
    if (lane == 0) sred[warp] = m;
    __syncthreads();
    m = sred[0];
#pragma unroll
    for (int w2 = 1; w2 < 8; w2++)
        m = fmaxf(m, sred[w2]);
    __syncthreads();

    x.x = __expf(x.x - m);
    x.y = __expf(x.y - m);
    x.z = __expf(x.z - m);
    x.w = __expf(x.w - m);
    float lsum = x.x + x.y + x.z + x.w;
#pragma unroll
    for (int off = 16; off; off >>= 1)
        lsum += __shfl_xor_sync(0xffffffffu, lsum, off);
    if (lane == 0) sred[warp] = lsum;
    __syncthreads();
    float tot = 0.f;
#pragma unroll
    for (int w2 = 0; w2 < 8; w2++)
        tot += sred[w2];
    const float inv = 1.f / tot;

    x.x *= inv; x.y *= inv; x.z *= inv; x.w *= inv;
    reinterpret_cast<float4*>(out + b * T_DIM)[tid] = x;

    // last softmax CTA resets counters for the next replay
    __threadfence();
    __syncthreads();
    if (threadIdx.x == 0) {
        unsigned old = atomicAdd(&g_sm_done, 1u);
        if (old == B_DIM - 1) {
            for (int i = 0; i < B_DIM; i++)
                g_cnt[i] = 0u;
            g_sm_done = 0u;
        }
    }
}

// ---------------------------------------------------------------------------
extern "C" void kernel_launch(void* const* d_in, const int* in_sizes, int n_in,
                              void* d_out, int out_size)
{
    const float* hid = (const float*)d_in[0];   // [1, B, H]
    const float* enc = (const float*)d_in[1];   // [T, B, H]
    const float* W   = (const float*)d_in[2];   // [H, H]
    // d_in[3] = bias: dropped — softmax shift-invariance makes it a no-op.
    float* out = (float*)d_out;                 // [B, 1, T]

    k1_proj_partial<<<dim3(H_DIM / 512, NSPL, B_DIM / BB), 128>>>(hid, W);
    k1b_reduce<<<(B_DIM * H_DIM) / 256, 256>>>();
    kB_energies_softmax<<<dim3(B_DIM, CHUNKS_PER_B + 1), 256>>>(enc, out);
}